// round 5
// baseline (speedup 1.0000x reference)
#include <cuda_runtime.h>
#include <math.h>
#include <stdint.h>

#define NB   2
#define NC   256
#define NHW  2304     // 48*48
#define NCH  12

#define TI   16       // gray pixels per attention block
#define TIW  4        // gray pixels per warp
#define TJ   32       // rgb pixels per smem tile (1 j per lane)
#define RSTR 260      // padded row stride (floats): conflict-free LDS.128
#define GX   12       // attention grid.x (stride loop handles overflow)
#define BUFF (TJ*RSTR)            // floats per rn buffer
#define ATTN_SMEM ((2*BUFF + TI*NC)*4 + TI*4 + 16)

// ---------------- scratch ----------------
__device__ int   d_cls_g[NB * NHW];
__device__ int   d_cls_r[NB * NHW];
__device__ int   d_list_g[NB * NCH * NHW];
__device__ int   d_list_r[NB * NCH * NHW];
__device__ int   d_cnt_g[NB * NCH];
__device__ int   d_cnt_r[NB * NCH];
__device__ float d_sum_g[NB * NCH * NC];   // class-masked channel SUMS
__device__ float d_sum_r[NB * NCH * NC];
__device__ float d_gn[NB * NHW * NC];      // unit vectors, [b][n][c]
__device__ float d_rn[NB * NHW * NC];

// packed f32x2 helpers
__device__ __forceinline__ void fma2(unsigned long long& d, unsigned long long a, unsigned long long b) {
    asm("fma.rn.f32x2 %0, %1, %2, %0;" : "+l"(d) : "l"(a), "l"(b));
}
__device__ __forceinline__ float hsum2(unsigned long long a, unsigned long long b) {
    unsigned long long s;
    asm("add.rn.f32x2 %0, %1, %2;" : "=l"(s) : "l"(a), "l"(b));
    float lo, hi;
    asm("mov.b64 {%0, %1}, %2;" : "=f"(lo), "=f"(hi) : "l"(s));
    return lo + hi;
}
// cp.async helpers
#define CP_ASYNC16(dst_u32, src_ptr) \
    asm volatile("cp.async.cg.shared.global [%0], [%1], 16;" :: "r"(dst_u32), "l"(src_ptr) : "memory")
#define CP_COMMIT() asm volatile("cp.async.commit_group;" ::: "memory")
#define CP_WAIT1()  asm volatile("cp.async.wait_group 1;" ::: "memory")

// ---------------- kernel 1: classify (per-pixel) + init canvas ----------------
__global__ void __launch_bounds__(256) k_classify(const float* __restrict__ gl,
                                                  const float* __restrict__ rl,
                                                  float* __restrict__ out) {
    int idx = blockIdx.x * 256 + threadIdx.x;          // 0 .. NB*NHW-1 (exact grid)
    out[idx]                = -1.0f;
    out[idx + NB * NHW]     = -1.0f;
    out[idx + 2 * NB * NHW] = -1.0f;

    int b = idx / NHW, n = idx - b * NHW;
    int kg = 0, kr = 0;
#pragma unroll
    for (int k = 0; k < NCH; k++) {
        if (gl[(b * NCH + k) * NHW + n] > 0.5f) kg = k;
        if (rl[(b * NCH + k) * NHW + n] > 0.5f) kr = k;
    }
    d_cls_g[idx] = kg;
    d_cls_r[idx] = kr;
}

// ---------------- kernel 2: fused lists (blocks 0..23) + masked sums (blocks 24..535) ----------------
__global__ void __launch_bounds__(512) k_prep(const float* __restrict__ gf, const float* __restrict__ rf) {
    int tid = threadIdx.x, lane = tid & 31, w = tid >> 5;

    if (blockIdx.x < NB * NCH) {
        int bk = blockIdx.x;
        int b = bk / NCH, k = bk - b * NCH;
        __shared__ int s_wsum[16];
        const int* clsg = d_cls_g + b * NHW;
        const int* clsr = d_cls_r + b * NHW;
        int* lg = d_list_g + (b * NCH + k) * NHW;
        int* lr = d_list_r + (b * NCH + k) * NHW;
        int base_g = 0, base_r = 0;
        for (int n0 = 0; n0 < NHW; n0 += 512) {
            int n = n0 + tid;
            int fg = (n < NHW) && (clsg[n] == k);
            unsigned bal = __ballot_sync(0xffffffffu, fg);
            int wp = __popc(bal & ((1u << lane) - 1u));
            if (lane == 0) s_wsum[w] = __popc(bal);
            __syncthreads();
            int woff = 0, tot = 0;
#pragma unroll
            for (int i = 0; i < 16; i++) { int v = s_wsum[i]; if (i < w) woff += v; tot += v; }
            if (fg) lg[base_g + woff + wp] = n;
            base_g += tot;
            __syncthreads();
            int fr = (n < NHW) && (clsr[n] == k);
            bal = __ballot_sync(0xffffffffu, fr);
            wp = __popc(bal & ((1u << lane) - 1u));
            if (lane == 0) s_wsum[w] = __popc(bal);
            __syncthreads();
            woff = 0; tot = 0;
#pragma unroll
            for (int i = 0; i < 16; i++) { int v = s_wsum[i]; if (i < w) woff += v; tot += v; }
            if (fr) lr[base_r + woff + wp] = n;
            base_r += tot;
            __syncthreads();
        }
        if (tid == 0) { d_cnt_g[b * NCH + k] = base_g; d_cnt_r[b * NCH + k] = base_r; }
    } else {
        int bc = blockIdx.x - NB * NCH;
        int b = bc >> 8, c = bc & 255;
        const float4* g4 = (const float4*)(gf + (b * NC + c) * NHW);
        const float4* r4 = (const float4*)(rf + (b * NC + c) * NHW);
        const int4* cg4 = (const int4*)(d_cls_g + b * NHW);
        const int4* cr4 = (const int4*)(d_cls_r + b * NHW);
        float sg[NCH], sr[NCH];
#pragma unroll
        for (int k = 0; k < NCH; k++) { sg[k] = 0.f; sr[k] = 0.f; }
        for (int q = tid; q < NHW / 4; q += 512) {
            float4 vg = g4[q], vr = r4[q];
            int4 kg = cg4[q], kr = cr4[q];
#pragma unroll
            for (int k = 0; k < NCH; k++) {
                sg[k] += (kg.x == k) ? vg.x : 0.f;
                sg[k] += (kg.y == k) ? vg.y : 0.f;
                sg[k] += (kg.z == k) ? vg.z : 0.f;
                sg[k] += (kg.w == k) ? vg.w : 0.f;
                sr[k] += (kr.x == k) ? vr.x : 0.f;
                sr[k] += (kr.y == k) ? vr.y : 0.f;
                sr[k] += (kr.z == k) ? vr.z : 0.f;
                sr[k] += (kr.w == k) ? vr.w : 0.f;
            }
        }
#pragma unroll
        for (int k = 0; k < NCH; k++) {
#pragma unroll
            for (int off = 16; off; off >>= 1) {
                sg[k] += __shfl_xor_sync(0xffffffffu, sg[k], off);
                sr[k] += __shfl_xor_sync(0xffffffffu, sr[k], off);
            }
        }
        __shared__ float sm[16][2 * NCH];
        if (lane == 0) {
#pragma unroll
            for (int k = 0; k < NCH; k++) { sm[w][k] = sg[k]; sm[w][NCH + k] = sr[k]; }
        }
        __syncthreads();
        if (tid < 2 * NCH) {
            float t = 0.f;
#pragma unroll
            for (int i = 0; i < 16; i++) t += sm[i][tid];
            int k = tid % NCH;
            if (tid >= NCH) d_sum_r[(b * NCH + k) * NC + c] = t;
            else            d_sum_g[(b * NCH + k) * NC + c] = t;
        }
    }
}

// ---------------- kernel 3: normalize + transpose ----------------
__global__ void __launch_bounds__(256) k_normalize(const float* __restrict__ gf, const float* __restrict__ rf) {
    __shared__ float tile[NC][33];
    int b = blockIdx.y;
    int p = blockIdx.z;
    int n0 = blockIdx.x * 32;
    int tid = threadIdx.x, lane = tid & 31, w = tid >> 5;
    const float* f    = (p == 0 ? gf : rf) + b * NC * NHW;
    const int*  cls   = (p == 0 ? d_cls_g : d_cls_r) + b * NHW;
    const float* sums = (p == 0 ? d_sum_g : d_sum_r) + b * NCH * NC;
    const int*  cnts  = (p == 0 ? d_cnt_g : d_cnt_r) + b * NCH;
    float* outp       = (p == 0 ? d_gn : d_rn) + b * NHW * NC;
#pragma unroll
    for (int it = 0; it < 8; it++) {
        int idx = tid + it * 256;
        int c = idx >> 3, q = idx & 7;
        float4 v = ((const float4*)(f + c * NHW + n0))[q];
        tile[c][q * 4 + 0] = v.x;
        tile[c][q * 4 + 1] = v.y;
        tile[c][q * 4 + 2] = v.z;
        tile[c][q * 4 + 3] = v.w;
    }
    __syncthreads();
#pragma unroll
    for (int q = 0; q < 4; q++) {
        int nn = w * 4 + q;
        int n = n0 + nn;
        int k = cls[n];
        float invc = 1.0f / fmaxf((float)cnts[k], 1.0f);
        const float* mk = sums + k * NC;
        float bar[8]; float ss = 0.f;
#pragma unroll
        for (int t = 0; t < 8; t++) {
            int c = lane + 32 * t;
            float v = tile[c][nn] - mk[c] * invc;
            bar[t] = v;
            ss += v * v;
        }
#pragma unroll
        for (int off = 16; off; off >>= 1) ss += __shfl_xor_sync(0xffffffffu, ss, off);
        float norm = sqrtf(ss);
        float inv = (norm > 0.f) ? (1.f / norm) : 1.f;
#pragma unroll
        for (int t = 0; t < 8; t++)
            outp[n * NC + lane + 32 * t] = bar[t] * inv;
    }
}

// ---------------- kernel 4: attention, cp.async double-buffered rn ----------------
__global__ void __launch_bounds__(128) k_attn(const float* __restrict__ img, float* __restrict__ out) {
    extern __shared__ __align__(16) float smem_dyn[];
    float* rn_s  = smem_dyn;                  // 2 * BUFF
    float* gn_s  = rn_s + 2 * BUFF;           // TI * NC
    int*   s_pix = (int*)(gn_s + TI * NC);    // TI

    int k = blockIdx.y + 1;
    int b = blockIdx.z;
    int cg = d_cnt_g[b * NCH + k], cr = d_cnt_r[b * NCH + k];
    if (cg < 2 || cr < 2) return;

    int tid = threadIdx.x, lane = tid & 31, w = tid >> 5;
    const int* lg = d_list_g + (b * NCH + k) * NHW;
    const int* lr = d_list_r + (b * NCH + k) * NHW;
    const float4* gn4 = (const float4*)(d_gn + b * NHW * NC);
    const float4* rn4 = (const float4*)(d_rn + b * NHW * NC);
    const float* imgb = img + b * 3 * NHW;

    uint32_t rn_su = (uint32_t)__cvta_generic_to_shared(rn_s);
    // per-thread fill slots: idx = tid + it*128, row = idx>>6, col4 = idx&63 (16 slots: TJ*64/128)
    int my_row0 = tid >> 6;          // 0 or 1; rows covered: my_row0 + 2*it
    int my_col4 = tid & 63;

    int nTiles = (cr + TJ - 1) / TJ;

    for (int i_base = blockIdx.x * TI; i_base < cg; i_base += GX * TI) {
        __syncthreads();
        if (tid < TI) s_pix[tid] = lg[min(i_base + tid, cg - 1)];
        __syncthreads();
#pragma unroll
        for (int it = 0; it < (TI * 64) / 128; it++) {
            int idx = tid + it * 128;
            int row = idx >> 6, col4 = idx & 63;
            ((float4*)gn_s)[idx] = gn4[s_pix[row] * 64 + col4];
        }

        float m[TIW], sden[TIW], a0[TIW], a1[TIW], a2[TIW];
#pragma unroll
        for (int ii = 0; ii < TIW; ii++) { m[ii] = -1e30f; sden[ii] = 0.f; a0[ii] = 0.f; a1[ii] = 0.f; a2[ii] = 0.f; }

        // ---- prologue: issue tile 0 into buffer 0 ----
        {
            int jp[16];
#pragma unroll
            for (int it = 0; it < 16; it++) {
                int row = my_row0 + 2 * it;
                jp[it] = __ldg(lr + min(row, cr - 1));
            }
#pragma unroll
            for (int it = 0; it < 16; it++) {
                int row = my_row0 + 2 * it;
                uint32_t dst = rn_su + (uint32_t)((row * RSTR + my_col4 * 4) * 4);
                CP_ASYNC16(dst, rn4 + (size_t)jp[it] * 64 + my_col4);
            }
            CP_COMMIT();
        }

        for (int t = 0; t < nTiles; t++) {
            int buf = t & 1;
            // issue tile t+1 into the other buffer (overwrites tile t-1; safe: sync at end of prev iter)
            if (t + 1 < nTiles) {
                int j0n = (t + 1) * TJ;
                int jp[16];
#pragma unroll
                for (int it = 0; it < 16; it++) {
                    int row = my_row0 + 2 * it;
                    jp[it] = __ldg(lr + min(j0n + row, cr - 1));
                }
                uint32_t base = rn_su + (uint32_t)((1 - buf) * BUFF * 4);
#pragma unroll
                for (int it = 0; it < 16; it++) {
                    int row = my_row0 + 2 * it;
                    uint32_t dst = base + (uint32_t)((row * RSTR + my_col4 * 4) * 4);
                    CP_ASYNC16(dst, rn4 + (size_t)jp[it] * 64 + my_col4);
                }
            }
            CP_COMMIT();
            CP_WAIT1();          // tile t landed (only t+1 group may remain pending)
            __syncthreads();     // tile t visible to all warps

            int j0 = t * TJ;
            bool v0 = (j0 + lane) < cr;
            int jl = __ldg(lr + min(j0 + lane, cr - 1));
            float i0 = __ldg(imgb + 0 * NHW + jl);
            float i1 = __ldg(imgb + 1 * NHW + jl);
            float i2 = __ldg(imgb + 2 * NHW + jl);

            unsigned long long accA[TIW], accB[TIW];
#pragma unroll
            for (int ii = 0; ii < TIW; ii++) { accA[ii] = 0; accB[ii] = 0; }
            const ulonglong2* rp = (const ulonglong2*)(rn_s + buf * BUFF + lane * RSTR);
#pragma unroll 4
            for (int c4 = 0; c4 < NC / 4; c4++) {
                ulonglong2 r = rp[c4];
#pragma unroll
                for (int ii = 0; ii < TIW; ii++) {
                    ulonglong2 g = ((const ulonglong2*)(gn_s + (w * TIW + ii) * NC))[c4];
                    fma2(accA[ii], r.x, g.x);
                    fma2(accB[ii], r.y, g.y);
                }
            }
#pragma unroll
            for (int ii = 0; ii < TIW; ii++) {
                float dA = hsum2(accA[ii], accB[ii]);
                float nm = m[ii];
                if (v0) nm = fmaxf(nm, dA);
                float sc = __expf(m[ii] - nm);
                float e0 = v0 ? __expf(dA - nm) : 0.f;
                sden[ii] = sden[ii] * sc + e0;
                a0[ii] = a0[ii] * sc + e0 * i0;
                a1[ii] = a1[ii] * sc + e0 * i1;
                a2[ii] = a2[ii] * sc + e0 * i2;
                m[ii] = nm;
            }
            __syncthreads();     // all done reading buf before next iter overwrites it
        }

        // cross-lane merge, then write
#pragma unroll
        for (int ii = 0; ii < TIW; ii++) {
            float m_ = m[ii], s_ = sden[ii], x = a0[ii], y = a1[ii], z = a2[ii];
#pragma unroll
            for (int off = 16; off; off >>= 1) {
                float m2 = __shfl_xor_sync(0xffffffffu, m_, off);
                float s2 = __shfl_xor_sync(0xffffffffu, s_, off);
                float x2 = __shfl_xor_sync(0xffffffffu, x, off);
                float y2 = __shfl_xor_sync(0xffffffffu, y, off);
                float z2 = __shfl_xor_sync(0xffffffffu, z, off);
                float M  = fmaxf(m_, m2);
                float c1 = __expf(m_ - M), c2 = __expf(m2 - M);
                s_ = s_ * c1 + s2 * c2;
                x  = x  * c1 + x2 * c2;
                y  = y  * c1 + y2 * c2;
                z  = z  * c1 + z2 * c2;
                m_ = M;
            }
            int ig = i_base + w * TIW + ii;
            if (lane == 0 && ig < cg) {
                int pix = s_pix[w * TIW + ii];
                float inv = 1.f / s_;
                out[b * 3 * NHW + 0 * NHW + pix] = x * inv;
                out[b * 3 * NHW + 1 * NHW + pix] = y * inv;
                out[b * 3 * NHW + 2 * NHW + pix] = z * inv;
            }
        }
    }
}

// ---------------- launch ----------------
extern "C" void kernel_launch(void* const* d_in, const int* in_sizes, int n_in,
                              void* d_out, int out_size) {
    (void)in_sizes; (void)n_in; (void)out_size;
    const float* gf  = (const float*)d_in[0];
    const float* rf  = (const float*)d_in[1];
    const float* img = (const float*)d_in[2];
    const float* gl  = (const float*)d_in[3];
    const float* rl  = (const float*)d_in[4];
    float* out = (float*)d_out;

    cudaFuncSetAttribute(k_attn, cudaFuncAttributeMaxDynamicSharedMemorySize, ATTN_SMEM);

    k_classify<<<NB * NHW / 256, 256>>>(gl, rl, out);
    k_prep<<<NB * NCH + NB * NC, 512>>>(gf, rf);
    k_normalize<<<dim3(NHW / 32, NB, 2), 256>>>(gf, rf);
    k_attn<<<dim3(GX, NCH - 1, NB), 128, ATTN_SMEM>>>(img, out);
}

// round 6
// speedup vs baseline: 1.1235x; 1.1235x over previous
#include <cuda_runtime.h>
#include <math.h>
#include <stdint.h>

#define NB   2
#define NC   256
#define NHW  2304     // 48*48
#define NCH  12

#define TI   16       // gray pixels per attention block
#define TIW  4        // gray pixels per warp
#define TJC  32       // rgb pixels per smem tile
#define CH   128      // channel half per sub-tile
#define CSTR 132      // padded row stride (floats) for a 128-float row: conflict-free LDS.128
#define BUFC (TJC*CSTR)           // floats per rn buffer (4224)
#define GX   12       // attention grid.x (i-chunk stride loop)
#define JS   2        // j segments

#define ATTN_SMEM ((2*BUFC + TI*NC)*4 + TI*4 + 16)

// ---------------- scratch ----------------
__device__ int    d_cls_g[NB * NHW];
__device__ int    d_cls_r[NB * NHW];
__device__ int    d_list_g[NB * NCH * NHW];
__device__ int    d_list_r[NB * NCH * NHW];
__device__ int    d_cnt_g[NB * NCH];
__device__ int    d_cnt_r[NB * NCH];
__device__ float  d_sum_g[NB * NCH * NC];
__device__ float  d_sum_r[NB * NCH * NC];
__device__ float  d_gn[NB * NHW * NC];     // unit vectors, [b][n][c]
__device__ float  d_rn[NB * NHW * NC];
__device__ float4 d_part[NB * NCH * NHW * JS];  // per-(i,seg) partial (s, a0, a1, a2)

// packed f32x2 helpers
__device__ __forceinline__ void fma2(unsigned long long& d, unsigned long long a, unsigned long long b) {
    asm("fma.rn.f32x2 %0, %1, %2, %0;" : "+l"(d) : "l"(a), "l"(b));
}
__device__ __forceinline__ float hsum2(unsigned long long a, unsigned long long b) {
    unsigned long long s;
    asm("add.rn.f32x2 %0, %1, %2;" : "=l"(s) : "l"(a), "l"(b));
    float lo, hi;
    asm("mov.b64 {%0, %1}, %2;" : "=f"(lo), "=f"(hi) : "l"(s));
    return lo + hi;
}
#define CP_ASYNC16(dst_u32, src_ptr) \
    asm volatile("cp.async.cg.shared.global [%0], [%1], 16;" :: "r"(dst_u32), "l"(src_ptr) : "memory")
#define CP_COMMIT() asm volatile("cp.async.commit_group;" ::: "memory")
#define CP_WAIT1()  asm volatile("cp.async.wait_group 1;" ::: "memory")

// ---------------- kernel 1: classify (per-pixel) + init canvas ----------------
__global__ void __launch_bounds__(256) k_classify(const float* __restrict__ gl,
                                                  const float* __restrict__ rl,
                                                  float* __restrict__ out) {
    int idx = blockIdx.x * 256 + threadIdx.x;          // exact grid: NB*NHW
    out[idx]                = -1.0f;
    out[idx + NB * NHW]     = -1.0f;
    out[idx + 2 * NB * NHW] = -1.0f;

    int b = idx / NHW, n = idx - b * NHW;
    int kg = 0, kr = 0;
#pragma unroll
    for (int k = 0; k < NCH; k++) {
        if (gl[(b * NCH + k) * NHW + n] > 0.5f) kg = k;
        if (rl[(b * NCH + k) * NHW + n] > 0.5f) kr = k;
    }
    d_cls_g[idx] = kg;
    d_cls_r[idx] = kr;
}

// ---------------- kernel 2: fused lists + masked sums ----------------
__global__ void __launch_bounds__(512) k_prep(const float* __restrict__ gf, const float* __restrict__ rf) {
    int tid = threadIdx.x, lane = tid & 31, w = tid >> 5;

    if (blockIdx.x < NB * NCH) {
        int bk = blockIdx.x;
        int b = bk / NCH, k = bk - b * NCH;
        __shared__ int s_wsum[16];
        const int* clsg = d_cls_g + b * NHW;
        const int* clsr = d_cls_r + b * NHW;
        int* lg = d_list_g + (b * NCH + k) * NHW;
        int* lr = d_list_r + (b * NCH + k) * NHW;
        int base_g = 0, base_r = 0;
        for (int n0 = 0; n0 < NHW; n0 += 512) {
            int n = n0 + tid;
            int fg = (n < NHW) && (clsg[n] == k);
            unsigned bal = __ballot_sync(0xffffffffu, fg);
            int wp = __popc(bal & ((1u << lane) - 1u));
            if (lane == 0) s_wsum[w] = __popc(bal);
            __syncthreads();
            int woff = 0, tot = 0;
#pragma unroll
            for (int i = 0; i < 16; i++) { int v = s_wsum[i]; if (i < w) woff += v; tot += v; }
            if (fg) lg[base_g + woff + wp] = n;
            base_g += tot;
            __syncthreads();
            int fr = (n < NHW) && (clsr[n] == k);
            bal = __ballot_sync(0xffffffffu, fr);
            wp = __popc(bal & ((1u << lane) - 1u));
            if (lane == 0) s_wsum[w] = __popc(bal);
            __syncthreads();
            woff = 0; tot = 0;
#pragma unroll
            for (int i = 0; i < 16; i++) { int v = s_wsum[i]; if (i < w) woff += v; tot += v; }
            if (fr) lr[base_r + woff + wp] = n;
            base_r += tot;
            __syncthreads();
        }
        if (tid == 0) { d_cnt_g[b * NCH + k] = base_g; d_cnt_r[b * NCH + k] = base_r; }
    } else {
        int bc = blockIdx.x - NB * NCH;
        int b = bc >> 8, c = bc & 255;
        const float4* g4 = (const float4*)(gf + (b * NC + c) * NHW);
        const float4* r4 = (const float4*)(rf + (b * NC + c) * NHW);
        const int4* cg4 = (const int4*)(d_cls_g + b * NHW);
        const int4* cr4 = (const int4*)(d_cls_r + b * NHW);
        float sg[NCH], sr[NCH];
#pragma unroll
        for (int k = 0; k < NCH; k++) { sg[k] = 0.f; sr[k] = 0.f; }
        for (int q = tid; q < NHW / 4; q += 512) {
            float4 vg = g4[q], vr = r4[q];
            int4 kg = cg4[q], kr = cr4[q];
#pragma unroll
            for (int k = 0; k < NCH; k++) {
                sg[k] += (kg.x == k) ? vg.x : 0.f;
                sg[k] += (kg.y == k) ? vg.y : 0.f;
                sg[k] += (kg.z == k) ? vg.z : 0.f;
                sg[k] += (kg.w == k) ? vg.w : 0.f;
                sr[k] += (kr.x == k) ? vr.x : 0.f;
                sr[k] += (kr.y == k) ? vr.y : 0.f;
                sr[k] += (kr.z == k) ? vr.z : 0.f;
                sr[k] += (kr.w == k) ? vr.w : 0.f;
            }
        }
#pragma unroll
        for (int k = 0; k < NCH; k++) {
#pragma unroll
            for (int off = 16; off; off >>= 1) {
                sg[k] += __shfl_xor_sync(0xffffffffu, sg[k], off);
                sr[k] += __shfl_xor_sync(0xffffffffu, sr[k], off);
            }
        }
        __shared__ float sm[16][2 * NCH];
        if (lane == 0) {
#pragma unroll
            for (int k = 0; k < NCH; k++) { sm[w][k] = sg[k]; sm[w][NCH + k] = sr[k]; }
        }
        __syncthreads();
        if (tid < 2 * NCH) {
            float t = 0.f;
#pragma unroll
            for (int i = 0; i < 16; i++) t += sm[i][tid];
            int k = tid % NCH;
            if (tid >= NCH) d_sum_r[(b * NCH + k) * NC + c] = t;
            else            d_sum_g[(b * NCH + k) * NC + c] = t;
        }
    }
}

// ---------------- kernel 3: normalize + transpose ----------------
__global__ void __launch_bounds__(256) k_normalize(const float* __restrict__ gf, const float* __restrict__ rf) {
    __shared__ float tile[NC][33];
    int b = blockIdx.y;
    int p = blockIdx.z;
    int n0 = blockIdx.x * 32;
    int tid = threadIdx.x, lane = tid & 31, w = tid >> 5;
    const float* f    = (p == 0 ? gf : rf) + b * NC * NHW;
    const int*  cls   = (p == 0 ? d_cls_g : d_cls_r) + b * NHW;
    const float* sums = (p == 0 ? d_sum_g : d_sum_r) + b * NCH * NC;
    const int*  cnts  = (p == 0 ? d_cnt_g : d_cnt_r) + b * NCH;
    float* outp       = (p == 0 ? d_gn : d_rn) + b * NHW * NC;
#pragma unroll
    for (int it = 0; it < 8; it++) {
        int idx = tid + it * 256;
        int c = idx >> 3, q = idx & 7;
        float4 v = ((const float4*)(f + c * NHW + n0))[q];
        tile[c][q * 4 + 0] = v.x;
        tile[c][q * 4 + 1] = v.y;
        tile[c][q * 4 + 2] = v.z;
        tile[c][q * 4 + 3] = v.w;
    }
    __syncthreads();
#pragma unroll
    for (int q = 0; q < 4; q++) {
        int nn = w * 4 + q;
        int n = n0 + nn;
        int k = cls[n];
        float invc = 1.0f / fmaxf((float)cnts[k], 1.0f);
        const float* mk = sums + k * NC;
        float bar[8]; float ss = 0.f;
#pragma unroll
        for (int t = 0; t < 8; t++) {
            int c = lane + 32 * t;
            float v = tile[c][nn] - mk[c] * invc;
            bar[t] = v;
            ss += v * v;
        }
#pragma unroll
        for (int off = 16; off; off >>= 1) ss += __shfl_xor_sync(0xffffffffu, ss, off);
        float norm = sqrtf(ss);
        float inv = (norm > 0.f) ? (1.f / norm) : 1.f;
#pragma unroll
        for (int t = 0; t < 8; t++)
            outp[n * NC + lane + 32 * t] = bar[t] * inv;
    }
}

// ---------------- kernel 4: attention partials (no-max softmax, j-split, c-tiled cp.async) ----------------
__global__ void __launch_bounds__(128) k_attn(const float* __restrict__ img) {
    extern __shared__ __align__(16) float smem_dyn[];
    float* rn_s  = smem_dyn;                  // 2 * BUFC
    float* gn_s  = rn_s + 2 * BUFC;           // TI * NC
    int*   s_pix = (int*)(gn_s + TI * NC);    // TI

    int yy = blockIdx.y;                      // 0..21
    int k   = (yy % (NCH - 1)) + 1;
    int seg = yy / (NCH - 1);
    int b = blockIdx.z;
    int cg = d_cnt_g[b * NCH + k], cr = d_cnt_r[b * NCH + k];
    if (cg < 2 || cr < 2) return;

    int tid = threadIdx.x, lane = tid & 31, w = tid >> 5;
    const int* lg = d_list_g + (b * NCH + k) * NHW;
    const int* lr = d_list_r + (b * NCH + k) * NHW;
    const float4* gn4 = (const float4*)(d_gn + b * NHW * NC);
    const float4* rn4 = (const float4*)(d_rn + b * NHW * NC);
    const float* imgb = img + b * 3 * NHW;
    float4* partp = d_part + (size_t)(b * NCH + k) * NHW * JS;

    uint32_t rn_su = (uint32_t)__cvta_generic_to_shared(rn_s);
    // fill slots: 1024 float4 per sub-tile, 8 per thread; row = idx>>5 (32 f4/row), col4 = idx&31
    int f_row0 = tid >> 5;      // rows: f_row0 + 4*it
    int f_col4 = tid & 31;

    int nT   = (cr + TJC - 1) / TJC;
    int tBeg = (seg * nT) / 2, tEnd = ((seg + 1) * nT) / 2;
    int sBeg = 2 * tBeg, nSub = 2 * (tEnd - tBeg);

    for (int i_base = blockIdx.x * TI; i_base < cg; i_base += GX * TI) {
        __syncthreads();
        if (tid < TI) s_pix[tid] = lg[min(i_base + tid, cg - 1)];
        __syncthreads();
#pragma unroll
        for (int it = 0; it < (TI * 64) / 128; it++) {
            int idx = tid + it * 128;
            int row = idx >> 6, col4 = idx & 63;
            ((float4*)gn_s)[idx] = gn4[s_pix[row] * 64 + col4];
        }

        float sden[TIW], a0[TIW], a1[TIW], a2[TIW];
#pragma unroll
        for (int ii = 0; ii < TIW; ii++) { sden[ii] = 0.f; a0[ii] = 0.f; a1[ii] = 0.f; a2[ii] = 0.f; }

        unsigned long long accA[TIW], accB[TIW];

        // prologue: issue first sub-tile into buffer 0
        if (nSub > 0) {
            int t = sBeg >> 1, h = sBeg & 1;
            int j0 = t * TJC;
#pragma unroll
            for (int it = 0; it < 8; it++) {
                int row = f_row0 + 4 * it;
                int jp = __ldg(lr + min(j0 + row, cr - 1));
                uint32_t dst = rn_su + (uint32_t)((row * CSTR + f_col4 * 4) * 4);
                CP_ASYNC16(dst, rn4 + (size_t)jp * 64 + h * 32 + f_col4);
            }
            CP_COMMIT();
        }

        for (int q = 0; q < nSub; q++) {
            int s = sBeg + q;
            int t = s >> 1, h = s & 1;
            int buf = q & 1;
            if (q + 1 < nSub) {
                int s2 = s + 1;
                int t2 = s2 >> 1, h2 = s2 & 1;
                int j0n = t2 * TJC;
                uint32_t base = rn_su + (uint32_t)((1 - buf) * BUFC * 4);
#pragma unroll
                for (int it = 0; it < 8; it++) {
                    int row = f_row0 + 4 * it;
                    int jp = __ldg(lr + min(j0n + row, cr - 1));
                    uint32_t dst = base + (uint32_t)((row * CSTR + f_col4 * 4) * 4);
                    CP_ASYNC16(dst, rn4 + (size_t)jp * 64 + h2 * 32 + f_col4);
                }
            }
            CP_COMMIT();
            CP_WAIT1();
            __syncthreads();

            if (h == 0) {
#pragma unroll
                for (int ii = 0; ii < TIW; ii++) { accA[ii] = 0; accB[ii] = 0; }
            }
            const ulonglong2* rp = (const ulonglong2*)(rn_s + buf * BUFC + lane * CSTR);
#pragma unroll 8
            for (int c4 = 0; c4 < CH / 4; c4++) {
                ulonglong2 r = rp[c4];
#pragma unroll
                for (int ii = 0; ii < TIW; ii++) {
                    ulonglong2 g = ((const ulonglong2*)(gn_s + (w * TIW + ii) * NC + h * CH))[c4];
                    fma2(accA[ii], r.x, g.x);
                    fma2(accB[ii], r.y, g.y);
                }
            }
            if (h == 1) {
                int j0 = t * TJC;
                bool v0 = (j0 + lane) < cr;
                int jl = __ldg(lr + min(j0 + lane, cr - 1));
                float i0 = __ldg(imgb + 0 * NHW + jl);
                float i1 = __ldg(imgb + 1 * NHW + jl);
                float i2 = __ldg(imgb + 2 * NHW + jl);
#pragma unroll
                for (int ii = 0; ii < TIW; ii++) {
                    float dA = hsum2(accA[ii], accB[ii]);
                    float e0 = v0 ? __expf(dA) : 0.f;   // logits bounded in [-1,1]: no max needed
                    sden[ii] += e0;
                    a0[ii] += e0 * i0;
                    a1[ii] += e0 * i1;
                    a2[ii] += e0 * i2;
                }
            }
            __syncthreads();
        }

        // cross-lane sum, write partial
#pragma unroll
        for (int ii = 0; ii < TIW; ii++) {
            float s_ = sden[ii], x = a0[ii], y = a1[ii], z = a2[ii];
#pragma unroll
            for (int off = 16; off; off >>= 1) {
                s_ += __shfl_xor_sync(0xffffffffu, s_, off);
                x  += __shfl_xor_sync(0xffffffffu, x, off);
                y  += __shfl_xor_sync(0xffffffffu, y, off);
                z  += __shfl_xor_sync(0xffffffffu, z, off);
            }
            int ig = i_base + w * TIW + ii;
            if (lane == 0 && ig < cg) {
                partp[ig * JS + seg] = make_float4(s_, x, y, z);
            }
        }
    }
}

// ---------------- kernel 5: merge partials, divide, scatter ----------------
__global__ void __launch_bounds__(256) k_merge(float* __restrict__ out) {
    int bk = blockIdx.x;                       // 0..21
    int b = bk / (NCH - 1), k = bk % (NCH - 1) + 1;
    int cg = d_cnt_g[b * NCH + k], cr = d_cnt_r[b * NCH + k];
    if (cg < 2 || cr < 2) return;
    const int* lg = d_list_g + (b * NCH + k) * NHW;
    const float4* partp = d_part + (size_t)(b * NCH + k) * NHW * JS;
    for (int i = threadIdx.x; i < cg; i += 256) {
        float4 P0 = partp[i * JS + 0];
        float4 P1 = partp[i * JS + 1];
        float inv = 1.0f / (P0.x + P1.x);
        int pix = lg[i];
        out[b * 3 * NHW + 0 * NHW + pix] = (P0.y + P1.y) * inv;
        out[b * 3 * NHW + 1 * NHW + pix] = (P0.z + P1.z) * inv;
        out[b * 3 * NHW + 2 * NHW + pix] = (P0.w + P1.w) * inv;
    }
}

// ---------------- launch ----------------
extern "C" void kernel_launch(void* const* d_in, const int* in_sizes, int n_in,
                              void* d_out, int out_size) {
    (void)in_sizes; (void)n_in; (void)out_size;
    const float* gf  = (const float*)d_in[0];
    const float* rf  = (const float*)d_in[1];
    const float* img = (const float*)d_in[2];
    const float* gl  = (const float*)d_in[3];
    const float* rl  = (const float*)d_in[4];
    float* out = (float*)d_out;

    cudaFuncSetAttribute(k_attn, cudaFuncAttributeMaxDynamicSharedMemorySize, ATTN_SMEM);

    k_classify<<<NB * NHW / 256, 256>>>(gl, rl, out);
    k_prep<<<NB * NCH + NB * NC, 512>>>(gf, rf);
    k_normalize<<<dim3(NHW / 32, NB, 2), 256>>>(gf, rf);
    k_attn<<<dim3(GX, (NCH - 1) * JS, NB), 128, ATTN_SMEM>>>(img);
    k_merge<<<NB * (NCH - 1), 256>>>(out);
}

// round 7
// speedup vs baseline: 1.4280x; 1.2709x over previous
#include <cuda_runtime.h>
#include <math.h>
#include <stdint.h>

#define NB   2
#define NC   256
#define NHW  2304     // 48*48
#define NCH  12

#define TI   32       // gray pixels per attention block (8 warps x TIW)
#define TIW  4        // gray pixels per warp
#define TJC  32       // rgb pixels per smem tile
#define CH   128      // channel half per sub-tile
#define CSTR 132      // padded row stride (floats): conflict-free LDS.128
#define BUFC (TJC*CSTR)           // floats per rn buffer (4224)
#define GX   7        // attention grid.x (i-chunk stride loop; 7*32=224 >= max cg)
#define JS   3        // j segments

#define ATTN_SMEM ((2*BUFC + TI*NC)*4 + TI*4 + 16)

// ---------------- scratch ----------------
__device__ int    d_cls_g[NB * NHW];
__device__ int    d_cls_r[NB * NHW];
__device__ int    d_list_g[NB * NCH * NHW];
__device__ int    d_list_r[NB * NCH * NHW];
__device__ int    d_cnt_g[NB * NCH];
__device__ int    d_cnt_r[NB * NCH];
__device__ float  d_sum_g[NB * NCH * NC];
__device__ float  d_sum_r[NB * NCH * NC];
__device__ float  d_gn[NB * NHW * NC];     // unit vectors, [b][n][c]
__device__ float  d_rn[NB * NHW * NC];
__device__ float4 d_part[NB * NCH * NHW * JS];  // per-(i,seg) partial (s, a0, a1, a2)

// packed f32x2 helpers
__device__ __forceinline__ void fma2(unsigned long long& d, unsigned long long a, unsigned long long b) {
    asm("fma.rn.f32x2 %0, %1, %2, %0;" : "+l"(d) : "l"(a), "l"(b));
}
__device__ __forceinline__ float hsum2(unsigned long long a, unsigned long long b) {
    unsigned long long s;
    asm("add.rn.f32x2 %0, %1, %2;" : "=l"(s) : "l"(a), "l"(b));
    float lo, hi;
    asm("mov.b64 {%0, %1}, %2;" : "=f"(lo), "=f"(hi) : "l"(s));
    return lo + hi;
}
#define CP_ASYNC16(dst_u32, src_ptr) \
    asm volatile("cp.async.cg.shared.global [%0], [%1], 16;" :: "r"(dst_u32), "l"(src_ptr) : "memory")
#define CP_COMMIT() asm volatile("cp.async.commit_group;" ::: "memory")
#define CP_WAIT1()  asm volatile("cp.async.wait_group 1;" ::: "memory")

// ---------------- kernel 1: classify (per-pixel) + init canvas ----------------
__global__ void __launch_bounds__(256) k_classify(const float* __restrict__ gl,
                                                  const float* __restrict__ rl,
                                                  float* __restrict__ out) {
    int idx = blockIdx.x * 256 + threadIdx.x;          // exact grid: NB*NHW
    out[idx]                = -1.0f;
    out[idx + NB * NHW]     = -1.0f;
    out[idx + 2 * NB * NHW] = -1.0f;

    int b = idx / NHW, n = idx - b * NHW;
    int kg = 0, kr = 0;
#pragma unroll
    for (int k = 0; k < NCH; k++) {
        if (gl[(b * NCH + k) * NHW + n] > 0.5f) kg = k;
        if (rl[(b * NCH + k) * NHW + n] > 0.5f) kr = k;
    }
    d_cls_g[idx] = kg;
    d_cls_r[idx] = kr;
}

// ---------------- kernel 2: fused lists + masked sums ----------------
__global__ void __launch_bounds__(512) k_prep(const float* __restrict__ gf, const float* __restrict__ rf) {
    int tid = threadIdx.x, lane = tid & 31, w = tid >> 5;

    if (blockIdx.x < NB * NCH) {
        int bk = blockIdx.x;
        int b = bk / NCH, k = bk - b * NCH;
        __shared__ int s_wsum[16];
        const int* clsg = d_cls_g + b * NHW;
        const int* clsr = d_cls_r + b * NHW;
        int* lg = d_list_g + (b * NCH + k) * NHW;
        int* lr = d_list_r + (b * NCH + k) * NHW;
        int base_g = 0, base_r = 0;
        for (int n0 = 0; n0 < NHW; n0 += 512) {
            int n = n0 + tid;
            int fg = (n < NHW) && (clsg[n] == k);
            unsigned bal = __ballot_sync(0xffffffffu, fg);
            int wp = __popc(bal & ((1u << lane) - 1u));
            if (lane == 0) s_wsum[w] = __popc(bal);
            __syncthreads();
            int woff = 0, tot = 0;
#pragma unroll
            for (int i = 0; i < 16; i++) { int v = s_wsum[i]; if (i < w) woff += v; tot += v; }
            if (fg) lg[base_g + woff + wp] = n;
            base_g += tot;
            __syncthreads();
            int fr = (n < NHW) && (clsr[n] == k);
            bal = __ballot_sync(0xffffffffu, fr);
            wp = __popc(bal & ((1u << lane) - 1u));
            if (lane == 0) s_wsum[w] = __popc(bal);
            __syncthreads();
            woff = 0; tot = 0;
#pragma unroll
            for (int i = 0; i < 16; i++) { int v = s_wsum[i]; if (i < w) woff += v; tot += v; }
            if (fr) lr[base_r + woff + wp] = n;
            base_r += tot;
            __syncthreads();
        }
        if (tid == 0) { d_cnt_g[b * NCH + k] = base_g; d_cnt_r[b * NCH + k] = base_r; }
    } else {
        int bc = blockIdx.x - NB * NCH;
        int b = bc >> 8, c = bc & 255;
        const float4* g4 = (const float4*)(gf + (b * NC + c) * NHW);
        const float4* r4 = (const float4*)(rf + (b * NC + c) * NHW);
        const int4* cg4 = (const int4*)(d_cls_g + b * NHW);
        const int4* cr4 = (const int4*)(d_cls_r + b * NHW);
        float sg[NCH], sr[NCH];
#pragma unroll
        for (int k = 0; k < NCH; k++) { sg[k] = 0.f; sr[k] = 0.f; }
        for (int q = tid; q < NHW / 4; q += 512) {
            float4 vg = g4[q], vr = r4[q];
            int4 kg = cg4[q], kr = cr4[q];
#pragma unroll
            for (int k = 0; k < NCH; k++) {
                sg[k] += (kg.x == k) ? vg.x : 0.f;
                sg[k] += (kg.y == k) ? vg.y : 0.f;
                sg[k] += (kg.z == k) ? vg.z : 0.f;
                sg[k] += (kg.w == k) ? vg.w : 0.f;
                sr[k] += (kr.x == k) ? vr.x : 0.f;
                sr[k] += (kr.y == k) ? vr.y : 0.f;
                sr[k] += (kr.z == k) ? vr.z : 0.f;
                sr[k] += (kr.w == k) ? vr.w : 0.f;
            }
        }
#pragma unroll
        for (int k = 0; k < NCH; k++) {
#pragma unroll
            for (int off = 16; off; off >>= 1) {
                sg[k] += __shfl_xor_sync(0xffffffffu, sg[k], off);
                sr[k] += __shfl_xor_sync(0xffffffffu, sr[k], off);
            }
        }
        __shared__ float sm[16][2 * NCH];
        if (lane == 0) {
#pragma unroll
            for (int k = 0; k < NCH; k++) { sm[w][k] = sg[k]; sm[w][NCH + k] = sr[k]; }
        }
        __syncthreads();
        if (tid < 2 * NCH) {
            float t = 0.f;
#pragma unroll
            for (int i = 0; i < 16; i++) t += sm[i][tid];
            int k = tid % NCH;
            if (tid >= NCH) d_sum_r[(b * NCH + k) * NC + c] = t;
            else            d_sum_g[(b * NCH + k) * NC + c] = t;
        }
    }
}

// ---------------- kernel 3: normalize + transpose ----------------
__global__ void __launch_bounds__(256) k_normalize(const float* __restrict__ gf, const float* __restrict__ rf) {
    __shared__ float tile[NC][33];
    int b = blockIdx.y;
    int p = blockIdx.z;
    int n0 = blockIdx.x * 32;
    int tid = threadIdx.x, lane = tid & 31, w = tid >> 5;
    const float* f    = (p == 0 ? gf : rf) + b * NC * NHW;
    const int*  cls   = (p == 0 ? d_cls_g : d_cls_r) + b * NHW;
    const float* sums = (p == 0 ? d_sum_g : d_sum_r) + b * NCH * NC;
    const int*  cnts  = (p == 0 ? d_cnt_g : d_cnt_r) + b * NCH;
    float* outp       = (p == 0 ? d_gn : d_rn) + b * NHW * NC;
#pragma unroll
    for (int it = 0; it < 8; it++) {
        int idx = tid + it * 256;
        int c = idx >> 3, q = idx & 7;
        float4 v = ((const float4*)(f + c * NHW + n0))[q];
        tile[c][q * 4 + 0] = v.x;
        tile[c][q * 4 + 1] = v.y;
        tile[c][q * 4 + 2] = v.z;
        tile[c][q * 4 + 3] = v.w;
    }
    __syncthreads();
#pragma unroll
    for (int q = 0; q < 4; q++) {
        int nn = w * 4 + q;
        int n = n0 + nn;
        int k = cls[n];
        float invc = 1.0f / fmaxf((float)cnts[k], 1.0f);
        const float* mk = sums + k * NC;
        float bar[8]; float ss = 0.f;
#pragma unroll
        for (int t = 0; t < 8; t++) {
            int c = lane + 32 * t;
            float v = tile[c][nn] - mk[c] * invc;
            bar[t] = v;
            ss += v * v;
        }
#pragma unroll
        for (int off = 16; off; off >>= 1) ss += __shfl_xor_sync(0xffffffffu, ss, off);
        float norm = sqrtf(ss);
        float inv = (norm > 0.f) ? (1.f / norm) : 1.f;
#pragma unroll
        for (int t = 0; t < 8; t++)
            outp[n * NC + lane + 32 * t] = bar[t] * inv;
    }
}

// ---------------- kernel 4: attention partials (8 warps, no-max softmax, j-split) ----------------
__global__ void __launch_bounds__(256, 3) k_attn(const float* __restrict__ img) {
    extern __shared__ __align__(16) float smem_dyn[];
    float* rn_s  = smem_dyn;                  // 2 * BUFC
    float* gn_s  = rn_s + 2 * BUFC;           // TI * NC
    int*   s_pix = (int*)(gn_s + TI * NC);    // TI

    int yy = blockIdx.y;                      // 0..32
    int k   = (yy % (NCH - 1)) + 1;
    int seg = yy / (NCH - 1);
    int b = blockIdx.z;
    int cg = d_cnt_g[b * NCH + k], cr = d_cnt_r[b * NCH + k];
    if (cg < 2 || cr < 2) return;

    int tid = threadIdx.x, lane = tid & 31, w = tid >> 5;   // w: 0..7
    const int* lg = d_list_g + (b * NCH + k) * NHW;
    const int* lr = d_list_r + (b * NCH + k) * NHW;
    const float4* gn4 = (const float4*)(d_gn + b * NHW * NC);
    const float4* rn4 = (const float4*)(d_rn + b * NHW * NC);
    const float* imgb = img + b * 3 * NHW;
    float4* partp = d_part + (size_t)(b * NCH + k) * NHW * JS;

    uint32_t rn_su = (uint32_t)__cvta_generic_to_shared(rn_s);
    // fill: 1024 float4 per sub-tile, 4 per thread; row = idx>>5, col4 = idx&31
    int f_row0 = tid >> 5;      // rows covered: f_row0 + 8*it
    int f_col4 = tid & 31;

    int nT   = (cr + TJC - 1) / TJC;
    int tBeg = (seg * nT) / JS, tEnd = ((seg + 1) * nT) / JS;
    int sBeg = 2 * tBeg, nSub = 2 * (tEnd - tBeg);

    for (int i_base = blockIdx.x * TI; i_base < cg; i_base += GX * TI) {
        __syncthreads();
        if (tid < TI) s_pix[tid] = lg[min(i_base + tid, cg - 1)];
        __syncthreads();
        // gn tile: TI*64 = 2048 float4, 8 per thread
#pragma unroll
        for (int it = 0; it < (TI * 64) / 256; it++) {
            int idx = tid + it * 256;
            int row = idx >> 6, col4 = idx & 63;
            ((float4*)gn_s)[idx] = gn4[s_pix[row] * 64 + col4];
        }

        float sden[TIW], a0[TIW], a1[TIW], a2[TIW];
#pragma unroll
        for (int ii = 0; ii < TIW; ii++) { sden[ii] = 0.f; a0[ii] = 0.f; a1[ii] = 0.f; a2[ii] = 0.f; }

        unsigned long long accA[TIW], accB[TIW];
        float i0 = 0.f, i1 = 0.f, i2 = 0.f;
        bool v0 = false;

        // prologue: issue first sub-tile into buffer 0
        if (nSub > 0) {
            int t = sBeg >> 1, h = sBeg & 1;
            int j0 = t * TJC;
#pragma unroll
            for (int it = 0; it < 4; it++) {
                int row = f_row0 + 8 * it;
                int jp = __ldg(lr + min(j0 + row, cr - 1));
                uint32_t dst = rn_su + (uint32_t)((row * CSTR + f_col4 * 4) * 4);
                CP_ASYNC16(dst, rn4 + (size_t)jp * 64 + h * 32 + f_col4);
            }
            CP_COMMIT();
        }

        for (int q = 0; q < nSub; q++) {
            int s = sBeg + q;
            int t = s >> 1, h = s & 1;
            int buf = q & 1;
            if (q + 1 < nSub) {
                int s2 = s + 1;
                int t2 = s2 >> 1, h2 = s2 & 1;
                int j0n = t2 * TJC;
                uint32_t base = rn_su + (uint32_t)((1 - buf) * BUFC * 4);
#pragma unroll
                for (int it = 0; it < 4; it++) {
                    int row = f_row0 + 8 * it;
                    int jp = __ldg(lr + min(j0n + row, cr - 1));
                    uint32_t dst = base + (uint32_t)((row * CSTR + f_col4 * 4) * 4);
                    CP_ASYNC16(dst, rn4 + (size_t)jp * 64 + h2 * 32 + f_col4);
                }
            }
            CP_COMMIT();
            CP_WAIT1();
            __syncthreads();

            if (h == 0) {
#pragma unroll
                for (int ii = 0; ii < TIW; ii++) { accA[ii] = 0; accB[ii] = 0; }
                // prefetch epilogue operands (used at h==1): hide L2 latency behind dot
                int j0 = t * TJC;
                v0 = (j0 + lane) < cr;
                int jl = __ldg(lr + min(j0 + lane, cr - 1));
                i0 = __ldg(imgb + 0 * NHW + jl);
                i1 = __ldg(imgb + 1 * NHW + jl);
                i2 = __ldg(imgb + 2 * NHW + jl);
            }
            const ulonglong2* rp = (const ulonglong2*)(rn_s + buf * BUFC + lane * CSTR);
#pragma unroll 8
            for (int c4 = 0; c4 < CH / 4; c4++) {
                ulonglong2 r = rp[c4];
#pragma unroll
                for (int ii = 0; ii < TIW; ii++) {
                    ulonglong2 g = ((const ulonglong2*)(gn_s + (w * TIW + ii) * NC + h * CH))[c4];
                    fma2(accA[ii], r.x, g.x);
                    fma2(accB[ii], r.y, g.y);
                }
            }
            if (h == 1) {
#pragma unroll
                for (int ii = 0; ii < TIW; ii++) {
                    float dA = hsum2(accA[ii], accB[ii]);
                    float e0 = v0 ? __expf(dA) : 0.f;   // logits bounded in [-1,1]: no max needed
                    sden[ii] += e0;
                    a0[ii] += e0 * i0;
                    a1[ii] += e0 * i1;
                    a2[ii] += e0 * i2;
                }
            }
            __syncthreads();
        }

        // cross-lane sum, write partial
#pragma unroll
        for (int ii = 0; ii < TIW; ii++) {
            float s_ = sden[ii], x = a0[ii], y = a1[ii], z = a2[ii];
#pragma unroll
            for (int off = 16; off; off >>= 1) {
                s_ += __shfl_xor_sync(0xffffffffu, s_, off);
                x  += __shfl_xor_sync(0xffffffffu, x, off);
                y  += __shfl_xor_sync(0xffffffffu, y, off);
                z  += __shfl_xor_sync(0xffffffffu, z, off);
            }
            int ig = i_base + w * TIW + ii;
            if (lane == 0 && ig < cg) {
                partp[ig * JS + seg] = make_float4(s_, x, y, z);
            }
        }
    }
}

// ---------------- kernel 5: merge partials, divide, scatter ----------------
__global__ void __launch_bounds__(256) k_merge(float* __restrict__ out) {
    int bk = blockIdx.x;                       // 0..21
    int b = bk / (NCH - 1), k = bk % (NCH - 1) + 1;
    int cg = d_cnt_g[b * NCH + k], cr = d_cnt_r[b * NCH + k];
    if (cg < 2 || cr < 2) return;
    const int* lg = d_list_g + (b * NCH + k) * NHW;
    const float4* partp = d_part + (size_t)(b * NCH + k) * NHW * JS;
    for (int i = threadIdx.x; i < cg; i += 256) {
        float4 P0 = partp[i * JS + 0];
        float4 P1 = partp[i * JS + 1];
        float4 P2 = partp[i * JS + 2];
        float inv = 1.0f / (P0.x + P1.x + P2.x);
        int pix = lg[i];
        out[b * 3 * NHW + 0 * NHW + pix] = (P0.y + P1.y + P2.y) * inv;
        out[b * 3 * NHW + 1 * NHW + pix] = (P0.z + P1.z + P2.z) * inv;
        out[b * 3 * NHW + 2 * NHW + pix] = (P0.w + P1.w + P2.w) * inv;
    }
}

// ---------------- launch ----------------
extern "C" void kernel_launch(void* const* d_in, const int* in_sizes, int n_in,
                              void* d_out, int out_size) {
    (void)in_sizes; (void)n_in; (void)out_size;
    const float* gf  = (const float*)d_in[0];
    const float* rf  = (const float*)d_in[1];
    const float* img = (const float*)d_in[2];
    const float* gl  = (const float*)d_in[3];
    const float* rl  = (const float*)d_in[4];
    float* out = (float*)d_out;

    cudaFuncSetAttribute(k_attn, cudaFuncAttributeMaxDynamicSharedMemorySize, ATTN_SMEM);

    k_classify<<<NB * NHW / 256, 256>>>(gl, rl, out);
    k_prep<<<NB * NCH + NB * NC, 512>>>(gf, rf);
    k_normalize<<<dim3(NHW / 32, NB, 2), 256>>>(gf, rf);
    k_attn<<<dim3(GX, (NCH - 1) * JS, NB), 256, ATTN_SMEM>>>(img);
    k_merge<<<NB * (NCH - 1), 256>>>(out);
}